// round 3
// baseline (speedup 1.0000x reference)
#include <cuda_runtime.h>
#include <math.h>

#define B_   64
#define D_   4096
#define H_   32
#define HKV_ 8
#define G_   4
#define DH_  128
#define W_   2048

// ---------------- scratch (device globals; no allocations allowed) ----------------
__device__ float g_q   [B_ * D_];            // q projections (RoPE'd in place)
__device__ float g_knew[B_ * HKV_ * DH_];    // new k (RoPE'd in place)
__device__ float g_vnew[B_ * HKV_ * DH_];    // new v
__device__ float g_attn[B_ * D_];            // attention output
__device__ float g_xo  [B_ * 2 * D_];        // concat([x, o_proj]) for gate GEMM

// ---------------- generic skinny GEMM: C[64,N] = A[64,K] @ B[N,K]^T ----------------
// block: 128 threads = (tx 0..7) x (ty 0..15); tile 64 rows x 32 cols; 4x4 micro-tile.
__global__ void gemm64(const float* __restrict__ A, int lda,
                       const float* __restrict__ Bm,
                       float* __restrict__ C, int ldc, int K) {
    __shared__ float As[64][33];
    __shared__ float Bs[32][33];
    const int tid = threadIdx.x;
    const int tx = tid & 7, ty = tid >> 3;
    const int n0 = blockIdx.x * 32;
    float acc[4][4] = {};

    for (int k0 = 0; k0 < K; k0 += 32) {
        #pragma unroll
        for (int i = 0; i < 16; i++) {
            int e = tid + i * 128;
            As[e >> 5][e & 31] = A[(e >> 5) * lda + k0 + (e & 31)];
        }
        #pragma unroll
        for (int i = 0; i < 8; i++) {
            int e = tid + i * 128;
            Bs[e >> 5][e & 31] = Bm[(size_t)(n0 + (e >> 5)) * K + k0 + (e & 31)];
        }
        __syncthreads();
        #pragma unroll
        for (int k = 0; k < 32; k++) {
            float a0 = As[ty*4+0][k], a1 = As[ty*4+1][k], a2 = As[ty*4+2][k], a3 = As[ty*4+3][k];
            float b0 = Bs[tx*4+0][k], b1 = Bs[tx*4+1][k], b2 = Bs[tx*4+2][k], b3 = Bs[tx*4+3][k];
            acc[0][0] += a0*b0; acc[0][1] += a0*b1; acc[0][2] += a0*b2; acc[0][3] += a0*b3;
            acc[1][0] += a1*b0; acc[1][1] += a1*b1; acc[1][2] += a1*b2; acc[1][3] += a1*b3;
            acc[2][0] += a2*b0; acc[2][1] += a2*b1; acc[2][2] += a2*b2; acc[2][3] += a2*b3;
            acc[3][0] += a3*b0; acc[3][1] += a3*b1; acc[3][2] += a3*b2; acc[3][3] += a3*b3;
        }
        __syncthreads();
    }
    #pragma unroll
    for (int i = 0; i < 4; i++)
        #pragma unroll
        for (int j = 0; j < 4; j++)
            C[(size_t)(ty*4+i) * ldc + n0 + tx*4 + j] = acc[i][j];
}

// ---------------- gate GEMM with fused final epilogue ----------------
// gatelin[64,4096] = xo[64,8192] @ gate_w[4096,8192]^T + gate_b
// out = x + sigmoid(gatelin) * o_proj        (o_proj = xo[:, 4096:])
__global__ void gemm64_gate(const float* __restrict__ A,       // g_xo, lda = 8192
                            const float* __restrict__ Bm,      // gate_w
                            const float* __restrict__ bias,    // gate_b
                            const float* __restrict__ x,       // input x
                            float* __restrict__ out) {
    __shared__ float As[64][33];
    __shared__ float Bs[32][33];
    const int K = 2 * D_;
    const int tid = threadIdx.x;
    const int tx = tid & 7, ty = tid >> 3;
    const int n0 = blockIdx.x * 32;
    float acc[4][4] = {};

    for (int k0 = 0; k0 < K; k0 += 32) {
        #pragma unroll
        for (int i = 0; i < 16; i++) {
            int e = tid + i * 128;
            As[e >> 5][e & 31] = A[(size_t)(e >> 5) * K + k0 + (e & 31)];
        }
        #pragma unroll
        for (int i = 0; i < 8; i++) {
            int e = tid + i * 128;
            Bs[e >> 5][e & 31] = Bm[(size_t)(n0 + (e >> 5)) * K + k0 + (e & 31)];
        }
        __syncthreads();
        #pragma unroll
        for (int k = 0; k < 32; k++) {
            float a0 = As[ty*4+0][k], a1 = As[ty*4+1][k], a2 = As[ty*4+2][k], a3 = As[ty*4+3][k];
            float b0 = Bs[tx*4+0][k], b1 = Bs[tx*4+1][k], b2 = Bs[tx*4+2][k], b3 = Bs[tx*4+3][k];
            acc[0][0] += a0*b0; acc[0][1] += a0*b1; acc[0][2] += a0*b2; acc[0][3] += a0*b3;
            acc[1][0] += a1*b0; acc[1][1] += a1*b1; acc[1][2] += a1*b2; acc[1][3] += a1*b3;
            acc[2][0] += a2*b0; acc[2][1] += a2*b1; acc[2][2] += a2*b2; acc[2][3] += a2*b3;
            acc[3][0] += a3*b0; acc[3][1] += a3*b1; acc[3][2] += a3*b2; acc[3][3] += a3*b3;
        }
        __syncthreads();
    }
    #pragma unroll
    for (int i = 0; i < 4; i++) {
        int m = ty*4 + i;
        #pragma unroll
        for (int j = 0; j < 4; j++) {
            int n = n0 + tx*4 + j;
            float z = acc[i][j] + bias[n];
            float gsig = 1.0f / (1.0f + __expf(-z));
            float oproj = A[(size_t)m * K + D_ + n];  // xo second half
            out[(size_t)m * D_ + n] = x[(size_t)m * D_ + n] + gsig * oproj;
        }
    }
}

// ---------------- RoPE on q (64x4096) and k_new (64x1024), interleaved pairs -------
__global__ void rope_kernel(float* __restrict__ q, float* __restrict__ kn,
                            const int* __restrict__ pos_p) {
    const int idx = blockIdx.x * 256 + threadIdx.x;
    const int total = B_ * (D_ / 2 + HKV_ * DH_ / 2);  // 64 * 2560
    if (idx >= total) return;
    const int row = idx / 2560;
    int p = idx - row * 2560;
    float* base;
    if (p < 2048) base = q + (size_t)row * D_;
    else { p -= 2048; base = kn + (size_t)row * HKV_ * DH_; }
    const int i = p & 63;  // pair index within head
    const float pos = (float)(*pos_p);
    const float inv = 1.0f / powf(10000.0f, (float)(2 * i) / 128.0f);
    const float ang = pos * inv;
    float s, c;
    sincosf(ang, &s, &c);
    const float x0 = base[2 * p], x1 = base[2 * p + 1];
    base[2 * p]     = x0 * c - x1 * s;
    base[2 * p + 1] = x0 * s + x1 * c;
}

// ---------------- copy x into first half of xo ----------------
__global__ void copy_x_kernel(const float* __restrict__ x, float* __restrict__ xo) {
    int idx = blockIdx.x * 256 + threadIdx.x;
    if (idx >= B_ * D_) return;
    int m = idx >> 12, n = idx & (D_ - 1);
    xo[(size_t)m * (2 * D_) + n] = x[idx];
}

// ---------------- attention: one block per (hkv, b); 256 threads (8 warps) ---------
// Effective keys: w=0..2046 -> cache slot w+1 (drop oldest); w=2047 -> k_new/v_new.
__global__ void attn_kernel(const float* __restrict__ q,
                            const float* __restrict__ knew,
                            const float* __restrict__ vnew,
                            const float* __restrict__ kc,
                            const float* __restrict__ vc,
                            float* __restrict__ out) {
    const int hkv = blockIdx.x, b = blockIdx.y;
    __shared__ float s[G_][W_];        // 32 KB scores/probs
    __shared__ float red[G_][64];
    __shared__ float o_acc[G_][DH_];
    __shared__ float sm[G_];
    const int tid = threadIdx.x;
    const int lane = tid & 31, warp = tid >> 5;

    for (int i = tid; i < G_ * DH_; i += 256) ((float*)o_acc)[i] = 0.0f;

    // q registers: 4 heads x 4 dims per lane
    float qr[G_][4];
    const float* qbase = q + (size_t)b * D_ + (size_t)hkv * G_ * DH_;
    #pragma unroll
    for (int g = 0; g < G_; g++) {
        float4 t = *(const float4*)(qbase + g * DH_ + lane * 4);
        qr[g][0] = t.x; qr[g][1] = t.y; qr[g][2] = t.z; qr[g][3] = t.w;
    }
    const float scale = 0.08838834764831845f;  // 128^-0.5
    const size_t cbase = ((size_t)b * HKV_ + hkv) * W_ * DH_;
    const float* knew_r = knew + ((size_t)b * HKV_ + hkv) * DH_;
    const float* vnew_r = vnew + ((size_t)b * HKV_ + hkv) * DH_;

    __syncthreads();  // o_acc zero visible before pass-2 atomics

    // ---- pass 1: scores ----
    for (int w = warp; w < W_; w += 8) {
        const float* krow = (w < W_ - 1) ? (kc + cbase + (size_t)(w + 1) * DH_) : knew_r;
        float4 kv = *(const float4*)(krow + lane * 4);
        float p0 = qr[0][0]*kv.x + qr[0][1]*kv.y + qr[0][2]*kv.z + qr[0][3]*kv.w;
        float p1 = qr[1][0]*kv.x + qr[1][1]*kv.y + qr[1][2]*kv.z + qr[1][3]*kv.w;
        float p2 = qr[2][0]*kv.x + qr[2][1]*kv.y + qr[2][2]*kv.z + qr[2][3]*kv.w;
        float p3 = qr[3][0]*kv.x + qr[3][1]*kv.y + qr[3][2]*kv.z + qr[3][3]*kv.w;
        #pragma unroll
        for (int off = 16; off; off >>= 1) {
            p0 += __shfl_xor_sync(0xffffffffu, p0, off);
            p1 += __shfl_xor_sync(0xffffffffu, p1, off);
            p2 += __shfl_xor_sync(0xffffffffu, p2, off);
            p3 += __shfl_xor_sync(0xffffffffu, p3, off);
        }
        if (lane == 0) {
            s[0][w] = p0 * scale; s[1][w] = p1 * scale;
            s[2][w] = p2 * scale; s[3][w] = p3 * scale;
        }
    }
    __syncthreads();

    // ---- softmax (64 threads per head) ----
    {
        const int g = tid >> 6, t = tid & 63;
        float lm = -1e30f;
        for (int i = t; i < W_; i += 64) lm = fmaxf(lm, s[g][i]);
        red[g][t] = lm;
        __syncthreads();
        for (int st = 32; st; st >>= 1) {
            if (t < st) red[g][t] = fmaxf(red[g][t], red[g][t + st]);
            __syncthreads();
        }
        const float m = red[g][0];
        float ls = 0.0f;
        for (int i = t; i < W_; i += 64) {
            float e = __expf(s[g][i] - m);
            s[g][i] = e;
            ls += e;
        }
        __syncthreads();  // everyone done reading red[g][0]
        red[g][t] = ls;
        __syncthreads();
        for (int st = 32; st; st >>= 1) {
            if (t < st) red[g][t] += red[g][t + st];
            __syncthreads();
        }
        if (t == 0) sm[g] = red[g][0];
        __syncthreads();
    }

    // ---- pass 2: p @ V ----
    float acc[G_][4] = {};
    for (int w = warp; w < W_; w += 8) {
        const float* vrow = (w < W_ - 1) ? (vc + cbase + (size_t)(w + 1) * DH_) : vnew_r;
        float4 vv = *(const float4*)(vrow + lane * 4);
        #pragma unroll
        for (int g = 0; g < G_; g++) {
            float p = s[g][w];
            acc[g][0] += p * vv.x; acc[g][1] += p * vv.y;
            acc[g][2] += p * vv.z; acc[g][3] += p * vv.w;
        }
    }
    #pragma unroll
    for (int g = 0; g < G_; g++) {
        atomicAdd(&o_acc[g][lane * 4 + 0], acc[g][0]);
        atomicAdd(&o_acc[g][lane * 4 + 1], acc[g][1]);
        atomicAdd(&o_acc[g][lane * 4 + 2], acc[g][2]);
        atomicAdd(&o_acc[g][lane * 4 + 3], acc[g][3]);
    }
    __syncthreads();

    float* obase = out + (size_t)b * D_ + (size_t)hkv * G_ * DH_;
    for (int i = tid; i < G_ * DH_; i += 256) {
        int g = i >> 7, d = i & 127;
        obase[g * DH_ + d] = o_acc[g][d] / sm[g];
    }
}

// ---------------- launch ----------------
extern "C" void kernel_launch(void* const* d_in, const int* in_sizes, int n_in,
                              void* d_out, int out_size) {
    const float* x   = (const float*)d_in[0];
    const float* kc  = (const float*)d_in[1];
    const float* vc  = (const float*)d_in[2];
    const float* Wq  = (const float*)d_in[3];
    const float* Wk  = (const float*)d_in[4];
    const float* Wv  = (const float*)d_in[5];
    const float* Wo  = (const float*)d_in[6];
    const float* gw  = (const float*)d_in[7];
    const float* gb  = (const float*)d_in[8];
    const int*   pos = (const int*)d_in[9];
    float* out = (float*)d_out;

    float *qb, *knb, *vnb, *attnb, *xob;
    cudaGetSymbolAddress((void**)&qb,    g_q);
    cudaGetSymbolAddress((void**)&knb,   g_knew);
    cudaGetSymbolAddress((void**)&vnb,   g_vnew);
    cudaGetSymbolAddress((void**)&attnb, g_attn);
    cudaGetSymbolAddress((void**)&xob,   g_xo);

    // QKV projections
    gemm64<<<D_ / 32, 128>>>(x, D_, Wq, qb, D_, D_);
    gemm64<<<(HKV_ * DH_) / 32, 128>>>(x, D_, Wk, knb, HKV_ * DH_, D_);
    gemm64<<<(HKV_ * DH_) / 32, 128>>>(x, D_, Wv, vnb, HKV_ * DH_, D_);

    // RoPE on q and k_new
    {
        int total = B_ * (D_ / 2 + HKV_ * DH_ / 2);
        rope_kernel<<<(total + 255) / 256, 256>>>(qb, knb, pos);
    }

    // Attention
    attn_kernel<<<dim3(HKV_, B_), 256>>>(qb, knb, vnb, kc, vc, attnb);

    // xo = concat([x, attn @ Wo^T])
    copy_x_kernel<<<(B_ * D_ + 255) / 256, 256>>>(x, xob);
    gemm64<<<D_ / 32, 128>>>(attnb, D_, Wo, xob + D_, 2 * D_, D_);

    // Gate GEMM + fused final epilogue
    gemm64_gate<<<D_ / 32, 128>>>(xob, gw, gb, x, out);
}

// round 5
// speedup vs baseline: 1.8219x; 1.8219x over previous
#include <cuda_runtime.h>
#include <math.h>

#define B_   64
#define D_   4096
#define H_   32
#define HKV_ 8
#define G_   4
#define DH_  128
#define W_   2048

// ---------------- scratch (device globals; no allocations allowed) ----------------
__device__ float g_q   [B_ * D_];            // q projections (RoPE'd in place)
__device__ float g_knew[B_ * HKV_ * DH_];    // new k (RoPE'd in place)
__device__ float g_vnew[B_ * HKV_ * DH_];    // new v
__device__ float g_attn[B_ * D_];            // attention output
__device__ float g_xo  [B_ * 2 * D_];        // concat([x, o_proj]) for gate GEMM

// ================= tf32 tensor-core GEMM: C[64,N] = A[64,K] @ W[N,K]^T ============
// 256 threads (8 warps), block tile 64(M) x 32(N), k-tile 32, double-buffered cp.async.
// warp grid: 4 (M) x 2 (N); warp tile 16x16 = 2x mma.m16n8k8.

__device__ __forceinline__ unsigned f2tf32(float x) {
    unsigned y;
    asm("cvt.rna.tf32.f32 %0, %1;" : "=r"(y) : "f"(x));
    return y;
}

__device__ __forceinline__ void mma_tf32(float& c0, float& c1, float& c2, float& c3,
                                         unsigned a0, unsigned a1, unsigned a2, unsigned a3,
                                         unsigned b0, unsigned b1) {
    asm volatile("mma.sync.aligned.m16n8k8.row.col.f32.tf32.tf32.f32 "
                 "{%0,%1,%2,%3}, {%4,%5,%6,%7}, {%8,%9}, {%0,%1,%2,%3};"
                 : "+f"(c0), "+f"(c1), "+f"(c2), "+f"(c3)
                 : "r"(a0), "r"(a1), "r"(a2), "r"(a3), "r"(b0), "r"(b1));
}

#define CP16(dst_smem_u32, src_ptr) \
    asm volatile("cp.async.cg.shared.global [%0], [%1], 16;" :: "r"(dst_smem_u32), "l"(src_ptr))

// Loads one 64x32 A tile + 32x32 W tile at k0 into smem buffer `buf`.
__device__ __forceinline__ void gemm_load_tile(
    float (*As)[64][36], float (*Bs)[32][36],
    const float* __restrict__ A, int lda,
    const float* __restrict__ Wm, int K, int n0, int k0, int buf, int tid)
{
    // A: 64x32 floats = 512 float4 -> 2 per thread
    #pragma unroll
    for (int j = 0; j < 2; j++) {
        int f = tid + j * 256;
        int row = f >> 3, c4 = f & 7;
        unsigned dst = (unsigned)__cvta_generic_to_shared(&As[buf][row][c4 * 4]);
        CP16(dst, A + (size_t)row * lda + k0 + c4 * 4);
    }
    // W: 32x32 floats = 256 float4 -> 1 per thread
    {
        int row = tid >> 3, c4 = tid & 7;
        unsigned dst = (unsigned)__cvta_generic_to_shared(&Bs[buf][row][c4 * 4]);
        CP16(dst, Wm + (size_t)(n0 + row) * K + k0 + c4 * 4);
    }
    asm volatile("cp.async.commit_group;");
}

// Core compute for one resident k-tile.
__device__ __forceinline__ void gemm_compute_tile(
    float (*As)[64][36], float (*Bs)[32][36], int buf,
    int m_off, int n_off, int gid, int tig, float acc[2][4])
{
    #pragma unroll
    for (int kk = 0; kk < 32; kk += 8) {
        unsigned a0 = f2tf32(As[buf][m_off + gid    ][kk + tig    ]);
        unsigned a1 = f2tf32(As[buf][m_off + gid + 8][kk + tig    ]);
        unsigned a2 = f2tf32(As[buf][m_off + gid    ][kk + tig + 4]);
        unsigned a3 = f2tf32(As[buf][m_off + gid + 8][kk + tig + 4]);
        #pragma unroll
        for (int t = 0; t < 2; t++) {
            int n = n_off + t * 8;
            unsigned b0 = f2tf32(Bs[buf][n + gid][kk + tig    ]);
            unsigned b1 = f2tf32(Bs[buf][n + gid][kk + tig + 4]);
            mma_tf32(acc[t][0], acc[t][1], acc[t][2], acc[t][3],
                     a0, a1, a2, a3, b0, b1);
        }
    }
}

__global__ __launch_bounds__(256) void gemm_tf32(
    const float* __restrict__ A, int lda,
    const float* __restrict__ Wm,
    float* __restrict__ C, int ldc, int K)
{
    __shared__ float As[2][64][36];
    __shared__ float Bs[2][32][36];
    const int tid = threadIdx.x;
    const int n0 = blockIdx.x * 32;
    const int lane = tid & 31, warp = tid >> 5;
    const int m_off = (warp & 3) * 16, n_off = (warp >> 2) * 16;
    const int gid = lane >> 2, tig = lane & 3;

    float acc[2][4] = {};
    const int T = K >> 5;

    gemm_load_tile(As, Bs, A, lda, Wm, K, n0, 0, 0, tid);
    int buf = 0;
    for (int t = 0; t < T; t++) {
        if (t + 1 < T) {
            gemm_load_tile(As, Bs, A, lda, Wm, K, n0, (t + 1) << 5, buf ^ 1, tid);
            asm volatile("cp.async.wait_group 1;");
        } else {
            asm volatile("cp.async.wait_group 0;");
        }
        __syncthreads();
        gemm_compute_tile(As, Bs, buf, m_off, n_off, gid, tig, acc);
        __syncthreads();
        buf ^= 1;
    }

    #pragma unroll
    for (int t = 0; t < 2; t++) {
        int row = m_off + gid;
        int col = n0 + n_off + t * 8 + 2 * tig;
        C[(size_t)row * ldc + col]           = acc[t][0];
        C[(size_t)row * ldc + col + 1]       = acc[t][1];
        C[(size_t)(row + 8) * ldc + col]     = acc[t][2];
        C[(size_t)(row + 8) * ldc + col + 1] = acc[t][3];
    }
}

// Gate GEMM with fused final epilogue:
// z = xo @ gate_w^T + gate_b ; out = x + sigmoid(z) * o_proj, o_proj = xo[:, 4096:]
__global__ __launch_bounds__(256) void gemm_tf32_gate(
    const float* __restrict__ A,     // g_xo, K = 8192
    const float* __restrict__ Wm,    // gate_w
    const float* __restrict__ bias,
    const float* __restrict__ x,
    float* __restrict__ out)
{
    __shared__ float As[2][64][36];
    __shared__ float Bs[2][32][36];
    const int K = 2 * D_;
    const int tid = threadIdx.x;
    const int n0 = blockIdx.x * 32;
    const int lane = tid & 31, warp = tid >> 5;
    const int m_off = (warp & 3) * 16, n_off = (warp >> 2) * 16;
    const int gid = lane >> 2, tig = lane & 3;

    float acc[2][4] = {};
    const int T = K >> 5;

    gemm_load_tile(As, Bs, A, K, Wm, K, n0, 0, 0, tid);
    int buf = 0;
    for (int t = 0; t < T; t++) {
        if (t + 1 < T) {
            gemm_load_tile(As, Bs, A, K, Wm, K, n0, (t + 1) << 5, buf ^ 1, tid);
            asm volatile("cp.async.wait_group 1;");
        } else {
            asm volatile("cp.async.wait_group 0;");
        }
        __syncthreads();
        gemm_compute_tile(As, Bs, buf, m_off, n_off, gid, tig, acc);
        __syncthreads();
        buf ^= 1;
    }

    #pragma unroll
    for (int t = 0; t < 2; t++) {
        #pragma unroll
        for (int rr = 0; rr < 2; rr++) {
            int row = m_off + gid + rr * 8;
            #pragma unroll
            for (int cc = 0; cc < 2; cc++) {
                int col = n0 + n_off + t * 8 + 2 * tig + cc;
                float z = acc[t][rr * 2 + cc] + bias[col];
                float gsig = 1.0f / (1.0f + __expf(-z));
                float oproj = A[(size_t)row * K + D_ + col];
                out[(size_t)row * D_ + col] = x[(size_t)row * D_ + col] + gsig * oproj;
            }
        }
    }
}

// ---------------- RoPE on q (64x4096) and k_new (64x1024), interleaved pairs -------
__global__ void rope_kernel(float* __restrict__ q, float* __restrict__ kn,
                            const int* __restrict__ pos_p) {
    const int idx = blockIdx.x * 256 + threadIdx.x;
    const int total = B_ * (D_ / 2 + HKV_ * DH_ / 2);  // 64 * 2560
    if (idx >= total) return;
    const int row = idx / 2560;
    int p = idx - row * 2560;
    float* base;
    if (p < 2048) base = q + (size_t)row * D_;
    else { p -= 2048; base = kn + (size_t)row * HKV_ * DH_; }
    const int i = p & 63;  // pair index within head
    const float pos = (float)(*pos_p);
    const float inv = 1.0f / powf(10000.0f, (float)(2 * i) / 128.0f);
    const float ang = pos * inv;
    float s, c;
    sincosf(ang, &s, &c);
    const float x0 = base[2 * p], x1 = base[2 * p + 1];
    base[2 * p]     = x0 * c - x1 * s;
    base[2 * p + 1] = x0 * s + x1 * c;
}

// ---------------- copy x into first half of xo ----------------
__global__ void copy_x_kernel(const float* __restrict__ x, float* __restrict__ xo) {
    int idx = blockIdx.x * 256 + threadIdx.x;
    if (idx >= B_ * D_) return;
    int m = idx >> 12, n = idx & (D_ - 1);
    xo[(size_t)m * (2 * D_) + n] = x[idx];
}

// ---------------- attention: one block per (hkv, b); 256 threads (8 warps) ---------
// Effective keys: w=0..2046 -> cache slot w+1 (drop oldest); w=2047 -> k_new/v_new.
__global__ void attn_kernel(const float* __restrict__ q,
                            const float* __restrict__ knew,
                            const float* __restrict__ vnew,
                            const float* __restrict__ kc,
                            const float* __restrict__ vc,
                            float* __restrict__ out) {
    const int hkv = blockIdx.x, b = blockIdx.y;
    __shared__ float s[G_][W_];        // 32 KB scores/probs
    __shared__ float red[G_][64];
    __shared__ float o_acc[G_][DH_];
    __shared__ float sm[G_];
    const int tid = threadIdx.x;
    const int lane = tid & 31, warp = tid >> 5;

    for (int i = tid; i < G_ * DH_; i += 256) ((float*)o_acc)[i] = 0.0f;

    // q registers: 4 heads x 4 dims per lane
    float qr[G_][4];
    const float* qbase = q + (size_t)b * D_ + (size_t)hkv * G_ * DH_;
    #pragma unroll
    for (int g = 0; g < G_; g++) {
        float4 t = *(const float4*)(qbase + g * DH_ + lane * 4);
        qr[g][0] = t.x; qr[g][1] = t.y; qr[g][2] = t.z; qr[g][3] = t.w;
    }
    const float scale = 0.08838834764831845f;  // 128^-0.5
    const size_t cbase = ((size_t)b * HKV_ + hkv) * W_ * DH_;
    const float* knew_r = knew + ((size_t)b * HKV_ + hkv) * DH_;
    const float* vnew_r = vnew + ((size_t)b * HKV_ + hkv) * DH_;

    __syncthreads();  // o_acc zero visible before pass-2 atomics

    // ---- pass 1: scores ----
    for (int w = warp; w < W_; w += 8) {
        const float* krow = (w < W_ - 1) ? (kc + cbase + (size_t)(w + 1) * DH_) : knew_r;
        float4 kv = *(const float4*)(krow + lane * 4);
        float p0 = qr[0][0]*kv.x + qr[0][1]*kv.y + qr[0][2]*kv.z + qr[0][3]*kv.w;
        float p1 = qr[1][0]*kv.x + qr[1][1]*kv.y + qr[1][2]*kv.z + qr[1][3]*kv.w;
        float p2 = qr[2][0]*kv.x + qr[2][1]*kv.y + qr[2][2]*kv.z + qr[2][3]*kv.w;
        float p3 = qr[3][0]*kv.x + qr[3][1]*kv.y + qr[3][2]*kv.z + qr[3][3]*kv.w;
        #pragma unroll
        for (int off = 16; off; off >>= 1) {
            p0 += __shfl_xor_sync(0xffffffffu, p0, off);
            p1 += __shfl_xor_sync(0xffffffffu, p1, off);
            p2 += __shfl_xor_sync(0xffffffffu, p2, off);
            p3 += __shfl_xor_sync(0xffffffffu, p3, off);
        }
        if (lane == 0) {
            s[0][w] = p0 * scale; s[1][w] = p1 * scale;
            s[2][w] = p2 * scale; s[3][w] = p3 * scale;
        }
    }
    __syncthreads();

    // ---- softmax (64 threads per head) ----
    {
        const int g = tid >> 6, t = tid & 63;
        float lm = -1e30f;
        for (int i = t; i < W_; i += 64) lm = fmaxf(lm, s[g][i]);
        red[g][t] = lm;
        __syncthreads();
        for (int st = 32; st; st >>= 1) {
            if (t < st) red[g][t] = fmaxf(red[g][t], red[g][t + st]);
            __syncthreads();
        }
        const float m = red[g][0];
        float ls = 0.0f;
        for (int i = t; i < W_; i += 64) {
            float e = __expf(s[g][i] - m);
            s[g][i] = e;
            ls += e;
        }
        __syncthreads();  // everyone done reading red[g][0]
        red[g][t] = ls;
        __syncthreads();
        for (int st = 32; st; st >>= 1) {
            if (t < st) red[g][t] += red[g][t + st];
            __syncthreads();
        }
        if (t == 0) sm[g] = red[g][0];
        __syncthreads();
    }

    // ---- pass 2: p @ V ----
    float acc[G_][4] = {};
    for (int w = warp; w < W_; w += 8) {
        const float* vrow = (w < W_ - 1) ? (vc + cbase + (size_t)(w + 1) * DH_) : vnew_r;
        float4 vv = *(const float4*)(vrow + lane * 4);
        #pragma unroll
        for (int g = 0; g < G_; g++) {
            float p = s[g][w];
            acc[g][0] += p * vv.x; acc[g][1] += p * vv.y;
            acc[g][2] += p * vv.z; acc[g][3] += p * vv.w;
        }
    }
    #pragma unroll
    for (int g = 0; g < G_; g++) {
        atomicAdd(&o_acc[g][lane * 4 + 0], acc[g][0]);
        atomicAdd(&o_acc[g][lane * 4 + 1], acc[g][1]);
        atomicAdd(&o_acc[g][lane * 4 + 2], acc[g][2]);
        atomicAdd(&o_acc[g][lane * 4 + 3], acc[g][3]);
    }
    __syncthreads();

    float* obase = out + (size_t)b * D_ + (size_t)hkv * G_ * DH_;
    for (int i = tid; i < G_ * DH_; i += 256) {
        int g = i >> 7, d = i & 127;
        obase[g * DH_ + d] = o_acc[g][d] / sm[g];
    }
}

// ---------------- launch ----------------
extern "C" void kernel_launch(void* const* d_in, const int* in_sizes, int n_in,
                              void* d_out, int out_size) {
    const float* x   = (const float*)d_in[0];
    const float* kc  = (const float*)d_in[1];
    const float* vc  = (const float*)d_in[2];
    const float* Wq  = (const float*)d_in[3];
    const float* Wk  = (const float*)d_in[4];
    const float* Wv  = (const float*)d_in[5];
    const float* Wo  = (const float*)d_in[6];
    const float* gw  = (const float*)d_in[7];
    const float* gb  = (const float*)d_in[8];
    const int*   pos = (const int*)d_in[9];
    float* out = (float*)d_out;

    float *qb, *knb, *vnb, *attnb, *xob;
    cudaGetSymbolAddress((void**)&qb,    g_q);
    cudaGetSymbolAddress((void**)&knb,   g_knew);
    cudaGetSymbolAddress((void**)&vnb,   g_vnew);
    cudaGetSymbolAddress((void**)&attnb, g_attn);
    cudaGetSymbolAddress((void**)&xob,   g_xo);

    // QKV projections (tf32 tensor cores)
    gemm_tf32<<<D_ / 32, 256>>>(x, D_, Wq, qb, D_, D_);
    gemm_tf32<<<(HKV_ * DH_) / 32, 256>>>(x, D_, Wk, knb, HKV_ * DH_, D_);
    gemm_tf32<<<(HKV_ * DH_) / 32, 256>>>(x, D_, Wv, vnb, HKV_ * DH_, D_);

    // RoPE on q and k_new
    {
        int total = B_ * (D_ / 2 + HKV_ * DH_ / 2);
        rope_kernel<<<(total + 255) / 256, 256>>>(qb, knb, pos);
    }

    // Attention
    attn_kernel<<<dim3(HKV_, B_), 256>>>(qb, knb, vnb, kc, vc, attnb);

    // xo = concat([x, attn @ Wo^T])
    copy_x_kernel<<<(B_ * D_ + 255) / 256, 256>>>(x, xob);
    gemm_tf32<<<D_ / 32, 256>>>(attnb, D_, Wo, xob + D_, 2 * D_, D_);

    // Gate GEMM + fused final epilogue
    gemm_tf32_gate<<<D_ / 32, 256>>>(xob, gw, gb, x, out);
}

// round 7
// speedup vs baseline: 2.3347x; 1.2815x over previous
#include <cuda_runtime.h>
#include <math.h>

#define B_   64
#define D_   4096
#define HKV_ 8
#define G_   4
#define DH_  128
#define W_   2048
#define STAGES 3

// ---------------- scratch (device globals; no allocations allowed) ----------------
__device__ float g_q    [B_ * D_];            // q projections (RoPE'd in place)
__device__ float g_knew [B_ * HKV_ * DH_];    // new k (RoPE'd in place)
__device__ float g_vnew [B_ * HKV_ * DH_];    // new v
__device__ float g_attn [B_ * D_];            // attention output
__device__ float g_oproj[B_ * D_];            // attn @ Wo^T

// ================= tf32 tensor-core GEMM machinery ============
// 256 threads (8 warps), block tile 64(M) x 32(N), k-tile 32, 3-stage cp.async.
// warp grid: 4 (M) x 2 (N); warp tile 16x16 = 2x mma.m16n8k8.
// Static shared: 3 * (64*36 + 32*36) * 4 = 41472 B (< 48 KB static limit).

__device__ __forceinline__ unsigned f2tf32(float x) {
    unsigned y;
    asm("cvt.rna.tf32.f32 %0, %1;" : "=r"(y) : "f"(x));
    return y;
}

__device__ __forceinline__ void mma_tf32(float& c0, float& c1, float& c2, float& c3,
                                         unsigned a0, unsigned a1, unsigned a2, unsigned a3,
                                         unsigned b0, unsigned b1) {
    asm volatile("mma.sync.aligned.m16n8k8.row.col.f32.tf32.tf32.f32 "
                 "{%0,%1,%2,%3}, {%4,%5,%6,%7}, {%8,%9}, {%0,%1,%2,%3};"
                 : "+f"(c0), "+f"(c1), "+f"(c2), "+f"(c3)
                 : "r"(a0), "r"(a1), "r"(a2), "r"(a3), "r"(b0), "r"(b1));
}

#define CP16(dst_smem_u32, src_ptr) \
    asm volatile("cp.async.cg.shared.global [%0], [%1], 16;" :: "r"(dst_smem_u32), "l"(src_ptr))

// Load one 64x32 A tile + 32x32 W tile into smem stage `buf`, commit a group.
__device__ __forceinline__ void load_tile(float As[STAGES][64][36], float Bs[STAGES][32][36],
                                          int buf,
                                          const float* __restrict__ Atile, int lda,
                                          const float* __restrict__ Wtile, int ldw, int tid)
{
    #pragma unroll
    for (int j = 0; j < 2; j++) {
        int f = tid + j * 256;
        int row = f >> 3, c4 = f & 7;
        unsigned dst = (unsigned)__cvta_generic_to_shared(&As[buf][row][c4 * 4]);
        CP16(dst, Atile + (size_t)row * lda + c4 * 4);
    }
    {
        int row = tid >> 3, c4 = tid & 7;
        unsigned dst = (unsigned)__cvta_generic_to_shared(&Bs[buf][row][c4 * 4]);
        CP16(dst, Wtile + (size_t)row * ldw + c4 * 4);
    }
    asm volatile("cp.async.commit_group;");
}

// Core compute for one resident k-tile.
__device__ __forceinline__ void compute_tile(float As[STAGES][64][36], float Bs[STAGES][32][36],
                                             int buf, int m_off, int n_off, int gid, int tig,
                                             float acc[2][4])
{
    #pragma unroll
    for (int kk = 0; kk < 32; kk += 8) {
        unsigned a0 = f2tf32(As[buf][m_off + gid    ][kk + tig    ]);
        unsigned a1 = f2tf32(As[buf][m_off + gid + 8][kk + tig    ]);
        unsigned a2 = f2tf32(As[buf][m_off + gid    ][kk + tig + 4]);
        unsigned a3 = f2tf32(As[buf][m_off + gid + 8][kk + tig + 4]);
        #pragma unroll
        for (int t = 0; t < 2; t++) {
            int n = n_off + t * 8;
            unsigned b0 = f2tf32(Bs[buf][n + gid][kk + tig    ]);
            unsigned b1 = f2tf32(Bs[buf][n + gid][kk + tig + 4]);
            mma_tf32(acc[t][0], acc[t][1], acc[t][2], acc[t][3],
                     a0, a1, a2, a3, b0, b1);
        }
    }
}

// ---------------- fused QKV projection: grid 192 ----------------
// blocks [0,128): q = x @ Wq^T ; [128,160): k_new = x @ Wk^T ; [160,192): v_new.
__global__ __launch_bounds__(256) void gemm_qkv(
    const float* __restrict__ x,
    const float* __restrict__ Wq, const float* __restrict__ Wk, const float* __restrict__ Wv,
    float* __restrict__ q, float* __restrict__ kn, float* __restrict__ vn)
{
    __shared__ float As[STAGES][64][36];
    __shared__ float Bs[STAGES][32][36];
    const int tid = threadIdx.x;
    const int bx = blockIdx.x;
    const float* Wm; float* C; int n0, ldc;
    if (bx < 128)      { Wm = Wq; C = q;  n0 = bx * 32;         ldc = D_; }
    else if (bx < 160) { Wm = Wk; C = kn; n0 = (bx - 128) * 32; ldc = HKV_ * DH_; }
    else               { Wm = Wv; C = vn; n0 = (bx - 160) * 32; ldc = HKV_ * DH_; }
    const int K = D_;
    const int lane = tid & 31, warp = tid >> 5;
    const int m_off = (warp & 3) * 16, n_off = (warp >> 2) * 16;
    const int gid = lane >> 2, tig = lane & 3;
    const float* W0 = Wm + (size_t)n0 * K;

    float acc[2][4] = {};
    const int T = K >> 5;  // 128

    load_tile(As, Bs, 0, x, K, W0, K, tid);
    load_tile(As, Bs, 1, x + 32, K, W0 + 32, K, tid);

    int buf = 0;
    for (int t = 0; t < T; t++) {
        asm volatile("cp.async.wait_group 1;");
        __syncthreads();
        compute_tile(As, Bs, buf, m_off, n_off, gid, tig, acc);
        int tn = t + 2;
        if (tn < T) {
            int nb = buf + 2; if (nb >= STAGES) nb -= STAGES;
            load_tile(As, Bs, nb, x + tn * 32, K, W0 + tn * 32, K, tid);
        } else {
            asm volatile("cp.async.commit_group;");
        }
        buf++; if (buf == STAGES) buf = 0;
    }

    #pragma unroll
    for (int t = 0; t < 2; t++) {
        int row = m_off + gid;
        int col = n0 + n_off + t * 8 + 2 * tig;
        C[(size_t)row * ldc + col]           = acc[t][0];
        C[(size_t)row * ldc + col + 1]       = acc[t][1];
        C[(size_t)(row + 8) * ldc + col]     = acc[t][2];
        C[(size_t)(row + 8) * ldc + col + 1] = acc[t][3];
    }
}

// ---------------- generic GEMM (used for Wo): C[64,4096] = A[64,4096] @ W^T --------
__global__ __launch_bounds__(256) void gemm_tf32(
    const float* __restrict__ A,
    const float* __restrict__ Wm,
    float* __restrict__ C)
{
    __shared__ float As[STAGES][64][36];
    __shared__ float Bs[STAGES][32][36];
    const int K = D_;
    const int tid = threadIdx.x;
    const int n0 = blockIdx.x * 32;
    const int lane = tid & 31, warp = tid >> 5;
    const int m_off = (warp & 3) * 16, n_off = (warp >> 2) * 16;
    const int gid = lane >> 2, tig = lane & 3;
    const float* W0 = Wm + (size_t)n0 * K;

    float acc[2][4] = {};
    const int T = K >> 5;

    load_tile(As, Bs, 0, A, K, W0, K, tid);
    load_tile(As, Bs, 1, A + 32, K, W0 + 32, K, tid);

    int buf = 0;
    for (int t = 0; t < T; t++) {
        asm volatile("cp.async.wait_group 1;");
        __syncthreads();
        compute_tile(As, Bs, buf, m_off, n_off, gid, tig, acc);
        int tn = t + 2;
        if (tn < T) {
            int nb = buf + 2; if (nb >= STAGES) nb -= STAGES;
            load_tile(As, Bs, nb, A + tn * 32, K, W0 + tn * 32, K, tid);
        } else {
            asm volatile("cp.async.commit_group;");
        }
        buf++; if (buf == STAGES) buf = 0;
    }

    #pragma unroll
    for (int t = 0; t < 2; t++) {
        int row = m_off + gid;
        int col = n0 + n_off + t * 8 + 2 * tig;
        C[(size_t)row * D_ + col]           = acc[t][0];
        C[(size_t)row * D_ + col + 1]       = acc[t][1];
        C[(size_t)(row + 8) * D_ + col]     = acc[t][2];
        C[(size_t)(row + 8) * D_ + col + 1] = acc[t][3];
    }
}

// ---------------- gate GEMM, A = concat([x, oproj]) read directly, fused epilogue --
// z = [x|oproj] @ gate_w^T + b ; out = x + sigmoid(z) * oproj
__global__ __launch_bounds__(256) void gemm_gate(
    const float* __restrict__ x,
    const float* __restrict__ oproj,
    const float* __restrict__ Wm,      // gate_w [4096, 8192]
    const float* __restrict__ bias,
    float* __restrict__ out)
{
    __shared__ float As[STAGES][64][36];
    __shared__ float Bs[STAGES][32][36];
    const int K = 2 * D_;
    const int tid = threadIdx.x;
    const int n0 = blockIdx.x * 32;
    const int lane = tid & 31, warp = tid >> 5;
    const int m_off = (warp & 3) * 16, n_off = (warp >> 2) * 16;
    const int gid = lane >> 2, tig = lane & 3;
    const float* W0 = Wm + (size_t)n0 * K;

    float acc[2][4] = {};
    const int T = K >> 5;  // 256

    // A-tile pointer for k-tile t: first 128 tiles from x, rest from oproj (both lda=4096)
    load_tile(As, Bs, 0, x, D_, W0, K, tid);
    load_tile(As, Bs, 1, x + 32, D_, W0 + 32, K, tid);

    int buf = 0;
    for (int t = 0; t < T; t++) {
        asm volatile("cp.async.wait_group 1;");
        __syncthreads();
        compute_tile(As, Bs, buf, m_off, n_off, gid, tig, acc);
        int tn = t + 2;
        if (tn < T) {
            int k0 = tn * 32;
            const float* Atile = (k0 < D_) ? (x + k0) : (oproj + (k0 - D_));
            int nb = buf + 2; if (nb >= STAGES) nb -= STAGES;
            load_tile(As, Bs, nb, Atile, D_, W0 + k0, K, tid);
        } else {
            asm volatile("cp.async.commit_group;");
        }
        buf++; if (buf == STAGES) buf = 0;
    }

    #pragma unroll
    for (int t = 0; t < 2; t++) {
        #pragma unroll
        for (int rr = 0; rr < 2; rr++) {
            int row = m_off + gid + rr * 8;
            #pragma unroll
            for (int cc = 0; cc < 2; cc++) {
                int col = n0 + n_off + t * 8 + 2 * tig + cc;
                float z = acc[t][rr * 2 + cc] + bias[col];
                float gsig = 1.0f / (1.0f + __expf(-z));
                float op = oproj[(size_t)row * D_ + col];
                out[(size_t)row * D_ + col] = x[(size_t)row * D_ + col] + gsig * op;
            }
        }
    }
}

// ---------------- RoPE on q (64x4096) and k_new (64x1024), interleaved pairs -------
__global__ void rope_kernel(float* __restrict__ q, float* __restrict__ kn,
                            const int* __restrict__ pos_p) {
    const int idx = blockIdx.x * 256 + threadIdx.x;
    const int total = B_ * (D_ / 2 + HKV_ * DH_ / 2);  // 64 * 2560
    if (idx >= total) return;
    const int row = idx / 2560;
    int p = idx - row * 2560;
    float* base;
    if (p < 2048) base = q + (size_t)row * D_;
    else { p -= 2048; base = kn + (size_t)row * HKV_ * DH_; }
    const int i = p & 63;  // pair index within head
    const float pos = (float)(*pos_p);
    const float inv = 1.0f / powf(10000.0f, (float)(2 * i) / 128.0f);
    const float ang = pos * inv;
    float s, c;
    sincosf(ang, &s, &c);
    const float x0 = base[2 * p], x1 = base[2 * p + 1];
    base[2 * p]     = x0 * c - x1 * s;
    base[2 * p + 1] = x0 * s + x1 * c;
}

// ---------------- attention: one block per (hkv, b); 256 threads (8 warps) ---------
// Effective keys: w=0..2046 -> cache slot w+1 (drop oldest); w=2047 -> k_new/v_new.
__global__ void attn_kernel(const float* __restrict__ q,
                            const float* __restrict__ knew,
                            const float* __restrict__ vnew,
                            const float* __restrict__ kc,
                            const float* __restrict__ vc,
                            float* __restrict__ out) {
    const int hkv = blockIdx.x, b = blockIdx.y;
    __shared__ float s[G_][W_];        // 32 KB scores/probs
    __shared__ float red[G_][64];
    __shared__ float o_acc[G_][DH_];
    __shared__ float sm[G_];
    const int tid = threadIdx.x;
    const int lane = tid & 31, warp = tid >> 5;

    for (int i = tid; i < G_ * DH_; i += 256) ((float*)o_acc)[i] = 0.0f;

    // q registers: 4 heads x 4 dims per lane
    float qr[G_][4];
    const float* qbase = q + (size_t)b * D_ + (size_t)hkv * G_ * DH_;
    #pragma unroll
    for (int g = 0; g < G_; g++) {
        float4 t = *(const float4*)(qbase + g * DH_ + lane * 4);
        qr[g][0] = t.x; qr[g][1] = t.y; qr[g][2] = t.z; qr[g][3] = t.w;
    }
    const float scale = 0.08838834764831845f;  // 128^-0.5
    const size_t cbase = ((size_t)b * HKV_ + hkv) * W_ * DH_;
    const float* knew_r = knew + ((size_t)b * HKV_ + hkv) * DH_;
    const float* vnew_r = vnew + ((size_t)b * HKV_ + hkv) * DH_;

    __syncthreads();  // o_acc zero visible before pass-2 atomics

    // ---- pass 1: scores (2 rows in flight per warp) ----
    for (int w = warp; w < W_; w += 16) {
        const int w2 = w + 8;
        const float* krow1 = (w  < W_ - 1) ? (kc + cbase + (size_t)(w  + 1) * DH_) : knew_r;
        const float* krow2 = (w2 < W_ - 1) ? (kc + cbase + (size_t)(w2 + 1) * DH_) : knew_r;
        float4 ka = *(const float4*)(krow1 + lane * 4);
        float4 kb = *(const float4*)(krow2 + lane * 4);
        float p0 = qr[0][0]*ka.x + qr[0][1]*ka.y + qr[0][2]*ka.z + qr[0][3]*ka.w;
        float p1 = qr[1][0]*ka.x + qr[1][1]*ka.y + qr[1][2]*ka.z + qr[1][3]*ka.w;
        float p2 = qr[2][0]*ka.x + qr[2][1]*ka.y + qr[2][2]*ka.z + qr[2][3]*ka.w;
        float p3 = qr[3][0]*ka.x + qr[3][1]*ka.y + qr[3][2]*ka.z + qr[3][3]*ka.w;
        float r0 = qr[0][0]*kb.x + qr[0][1]*kb.y + qr[0][2]*kb.z + qr[0][3]*kb.w;
        float r1 = qr[1][0]*kb.x + qr[1][1]*kb.y + qr[1][2]*kb.z + qr[1][3]*kb.w;
        float r2 = qr[2][0]*kb.x + qr[2][1]*kb.y + qr[2][2]*kb.z + qr[2][3]*kb.w;
        float r3 = qr[3][0]*kb.x + qr[3][1]*kb.y + qr[3][2]*kb.z + qr[3][3]*kb.w;
        #pragma unroll
        for (int off = 16; off; off >>= 1) {
            p0 += __shfl_xor_sync(0xffffffffu, p0, off);
            p1 += __shfl_xor_sync(0xffffffffu, p1, off);
            p2 += __shfl_xor_sync(0xffffffffu, p2, off);
            p3 += __shfl_xor_sync(0xffffffffu, p3, off);
            r0 += __shfl_xor_sync(0xffffffffu, r0, off);
            r1 += __shfl_xor_sync(0xffffffffu, r1, off);
            r2 += __shfl_xor_sync(0xffffffffu, r2, off);
            r3 += __shfl_xor_sync(0xffffffffu, r3, off);
        }
        if (lane == 0) {
            s[0][w]  = p0 * scale; s[1][w]  = p1 * scale;
            s[2][w]  = p2 * scale; s[3][w]  = p3 * scale;
            s[0][w2] = r0 * scale; s[1][w2] = r1 * scale;
            s[2][w2] = r2 * scale; s[3][w2] = r3 * scale;
        }
    }
    __syncthreads();

    // ---- softmax (64 threads per head) ----
    {
        const int g = tid >> 6, t = tid & 63;
        float lm = -1e30f;
        for (int i = t; i < W_; i += 64) lm = fmaxf(lm, s[g][i]);
        red[g][t] = lm;
        __syncthreads();
        for (int st = 32; st; st >>= 1) {
            if (t < st) red[g][t] = fmaxf(red[g][t], red[g][t + st]);
            __syncthreads();
        }
        const float m = red[g][0];
        float ls = 0.0f;
        for (int i = t; i < W_; i += 64) {
            float e = __expf(s[g][i] - m);
            s[g][i] = e;
            ls += e;
        }
        __syncthreads();  // everyone done reading red[g][0]
        red[g][t] = ls;
        __syncthreads();
        for (int st = 32; st; st >>= 1) {
            if (t < st) red[g][t] += red[g][t + st];
            __syncthreads();
        }
        if (t == 0) sm[g] = red[g][0];
        __syncthreads();
    }

    // ---- pass 2: p @ V (2 rows in flight per warp) ----
    float acc[G_][4] = {};
    for (int w = warp; w < W_; w += 16) {
        const int w2 = w + 8;
        const float* vrow1 = (w  < W_ - 1) ? (vc + cbase + (size_t)(w  + 1) * DH_) : vnew_r;
        const float* vrow2 = (w2 < W_ - 1) ? (vc + cbase + (size_t)(w2 + 1) * DH_) : vnew_r;
        float4 va = *(const float4*)(vrow1 + lane * 4);
        float4 vb = *(const float4*)(vrow2 + lane * 4);
        #pragma unroll
        for (int g = 0; g < G_; g++) {
            float pa = s[g][w], pb = s[g][w2];
            acc[g][0] += pa * va.x + pb * vb.x;
            acc[g][1] += pa * va.y + pb * vb.y;
            acc[g][2] += pa * va.z + pb * vb.z;
            acc[g][3] += pa * va.w + pb * vb.w;
        }
    }
    #pragma unroll
    for (int g = 0; g < G_; g++) {
        atomicAdd(&o_acc[g][lane * 4 + 0], acc[g][0]);
        atomicAdd(&o_acc[g][lane * 4 + 1], acc[g][1]);
        atomicAdd(&o_acc[g][lane * 4 + 2], acc[g][2]);
        atomicAdd(&o_acc[g][lane * 4 + 3], acc[g][3]);
    }
    __syncthreads();

    float* obase = out + (size_t)b * D_ + (size_t)hkv * G_ * DH_;
    for (int i = tid; i < G_ * DH_; i += 256) {
        int g = i >> 7, d = i & 127;
        obase[g * DH_ + d] = o_acc[g][d] / sm[g];
    }
}

// ---------------- launch ----------------
extern "C" void kernel_launch(void* const* d_in, const int* in_sizes, int n_in,
                              void* d_out, int out_size) {
    const float* x   = (const float*)d_in[0];
    const float* kc  = (const float*)d_in[1];
    const float* vc  = (const float*)d_in[2];
    const float* Wq  = (const float*)d_in[3];
    const float* Wk  = (const float*)d_in[4];
    const float* Wv  = (const float*)d_in[5];
    const float* Wo  = (const float*)d_in[6];
    const float* gw  = (const float*)d_in[7];
    const float* gb  = (const float*)d_in[8];
    const int*   pos = (const int*)d_in[9];
    float* out = (float*)d_out;

    float *qb, *knb, *vnb, *attnb, *opb;
    cudaGetSymbolAddress((void**)&qb,    g_q);
    cudaGetSymbolAddress((void**)&knb,   g_knew);
    cudaGetSymbolAddress((void**)&vnb,   g_vnew);
    cudaGetSymbolAddress((void**)&attnb, g_attn);
    cudaGetSymbolAddress((void**)&opb,   g_oproj);

    // Fused QKV projections (tf32 tensor cores, 3-stage cp.async), grid 192:
    // [0,128) q-tiles, [128,160) k-tiles, [160,192) v-tiles.
    gemm_qkv<<<192, 256>>>(x, Wq, Wk, Wv, qb, knb, vnb);

    // RoPE on q and k_new
    {
        int total = B_ * (D_ / 2 + HKV_ * DH_ / 2);
        rope_kernel<<<(total + 255) / 256, 256>>>(qb, knb, pos);
    }

    // Attention
    attn_kernel<<<dim3(HKV_, B_), 256>>>(qb, knb, vnb, kc, vc, attnb);

    // o_proj = attn @ Wo^T
    gemm_tf32<<<D_ / 32, 256>>>(attnb, Wo, opb);

    // Gate GEMM + fused final epilogue (reads x and oproj directly)
    gemm_gate<<<D_ / 32, 256>>>(x, opb, gw, gb, out);
}

// round 8
// speedup vs baseline: 3.0009x; 1.2853x over previous
#include <cuda_runtime.h>
#include <math.h>

#define B_   64
#define D_   4096
#define HKV_ 8
#define G_   4
#define DH_  128
#define W_   2048
#define STAGES 3
#define SK   4                     // split-K factor
#define QKV_N (D_ + 2 * HKV_ * DH_)   // 6144 concat output cols (q | knew | vnew)

// ---------------- scratch (device globals; no allocations allowed) ----------------
__device__ float g_q    [B_ * D_];             // q (RoPE'd)
__device__ float g_knew [B_ * HKV_ * DH_];     // new k (RoPE'd)
__device__ float g_vnew [B_ * HKV_ * DH_];     // new v
__device__ float g_attn [B_ * D_];             // attention output
__device__ float g_oproj[B_ * D_];             // attn @ Wo^T
__device__ float g_part [SK * B_ * QKV_N];     // split-K partials (reused by all GEMMs)

// ================= tf32 tensor-core GEMM machinery ============
// 256 threads (8 warps), block tile 64(M) x 32(N), k-tile 32, 3-stage cp.async.
// warp grid: 4 (M) x 2 (N); warp tile 16x16 = 2x mma.m16n8k8.

__device__ __forceinline__ unsigned f2tf32(float x) {
    unsigned y;
    asm("cvt.rna.tf32.f32 %0, %1;" : "=r"(y) : "f"(x));
    return y;
}

__device__ __forceinline__ void mma_tf32(float& c0, float& c1, float& c2, float& c3,
                                         unsigned a0, unsigned a1, unsigned a2, unsigned a3,
                                         unsigned b0, unsigned b1) {
    asm volatile("mma.sync.aligned.m16n8k8.row.col.f32.tf32.tf32.f32 "
                 "{%0,%1,%2,%3}, {%4,%5,%6,%7}, {%8,%9}, {%0,%1,%2,%3};"
                 : "+f"(c0), "+f"(c1), "+f"(c2), "+f"(c3)
                 : "r"(a0), "r"(a1), "r"(a2), "r"(a3), "r"(b0), "r"(b1));
}

#define CP16(dst_smem_u32, src_ptr) \
    asm volatile("cp.async.cg.shared.global [%0], [%1], 16;" :: "r"(dst_smem_u32), "l"(src_ptr))

__device__ __forceinline__ void load_tile(float As[STAGES][64][36], float Bs[STAGES][32][36],
                                          int buf,
                                          const float* __restrict__ Atile, int lda,
                                          const float* __restrict__ Wtile, int ldw, int tid)
{
    #pragma unroll
    for (int j = 0; j < 2; j++) {
        int f = tid + j * 256;
        int row = f >> 3, c4 = f & 7;
        unsigned dst = (unsigned)__cvta_generic_to_shared(&As[buf][row][c4 * 4]);
        CP16(dst, Atile + (size_t)row * lda + c4 * 4);
    }
    {
        int row = tid >> 3, c4 = tid & 7;
        unsigned dst = (unsigned)__cvta_generic_to_shared(&Bs[buf][row][c4 * 4]);
        CP16(dst, Wtile + (size_t)row * ldw + c4 * 4);
    }
    asm volatile("cp.async.commit_group;");
}

__device__ __forceinline__ void compute_tile(float As[STAGES][64][36], float Bs[STAGES][32][36],
                                             int buf, int m_off, int n_off, int gid, int tig,
                                             float acc[2][4])
{
    #pragma unroll
    for (int kk = 0; kk < 32; kk += 8) {
        unsigned a0 = f2tf32(As[buf][m_off + gid    ][kk + tig    ]);
        unsigned a1 = f2tf32(As[buf][m_off + gid + 8][kk + tig    ]);
        unsigned a2 = f2tf32(As[buf][m_off + gid    ][kk + tig + 4]);
        unsigned a3 = f2tf32(As[buf][m_off + gid + 8][kk + tig + 4]);
        #pragma unroll
        for (int t = 0; t < 2; t++) {
            int n = n_off + t * 8;
            unsigned b0 = f2tf32(Bs[buf][n + gid][kk + tig    ]);
            unsigned b1 = f2tf32(Bs[buf][n + gid][kk + tig + 4]);
            mma_tf32(acc[t][0], acc[t][1], acc[t][2], acc[t][3],
                     a0, a1, a2, a3, b0, b1);
        }
    }
}

// Store 64x32 partial accumulator block into partial buffer (row stride ldc).
__device__ __forceinline__ void store_partial(float* __restrict__ P, int ldc, int col0,
                                              int m_off, int n_off, int gid, int tig,
                                              float acc[2][4])
{
    #pragma unroll
    for (int t = 0; t < 2; t++) {
        int row = m_off + gid;
        int col = col0 + n_off + t * 8 + 2 * tig;
        P[(size_t)row * ldc + col]           = acc[t][0];
        P[(size_t)row * ldc + col + 1]       = acc[t][1];
        P[(size_t)(row + 8) * ldc + col]     = acc[t][2];
        P[(size_t)(row + 8) * ldc + col + 1] = acc[t][3];
    }
}

// ---------------- fused QKV projection, split-K: grid (192, SK) ----------------
// bx [0,128): q cols; [128,160): knew; [160,192): vnew. Partials layout:
// part[s][64][6144] with col concat (q | knew | vnew).
__global__ __launch_bounds__(256) void gemm_qkv_sk(
    const float* __restrict__ x,
    const float* __restrict__ Wq, const float* __restrict__ Wk, const float* __restrict__ Wv,
    float* __restrict__ part)
{
    __shared__ float As[STAGES][64][36];
    __shared__ float Bs[STAGES][32][36];
    const int tid = threadIdx.x;
    const int bx = blockIdx.x;
    const int split = blockIdx.y;
    const float* Wm; int n0, colbase;
    if (bx < 128)      { Wm = Wq; colbase = 0;    n0 = bx * 32; }
    else if (bx < 160) { Wm = Wk; colbase = D_;   n0 = (bx - 128) * 32; }
    else               { Wm = Wv; colbase = D_ + 1024; n0 = (bx - 160) * 32; }
    const int K = D_;
    const int Ks = K / SK;              // 1024
    const int koff = split * Ks;
    const int T = Ks >> 5;              // 32
    const int lane = tid & 31, warp = tid >> 5;
    const int m_off = (warp & 3) * 16, n_off = (warp >> 2) * 16;
    const int gid = lane >> 2, tig = lane & 3;
    const float* A0 = x + koff;
    const float* W0 = Wm + (size_t)n0 * K + koff;

    float acc[2][4] = {};

    load_tile(As, Bs, 0, A0, K, W0, K, tid);
    load_tile(As, Bs, 1, A0 + 32, K, W0 + 32, K, tid);

    int buf = 0;
    for (int t = 0; t < T; t++) {
        asm volatile("cp.async.wait_group 1;");
        __syncthreads();
        compute_tile(As, Bs, buf, m_off, n_off, gid, tig, acc);
        int tn = t + 2;
        if (tn < T) {
            int nb = buf + 2; if (nb >= STAGES) nb -= STAGES;
            load_tile(As, Bs, nb, A0 + tn * 32, K, W0 + tn * 32, K, tid);
        } else {
            asm volatile("cp.async.commit_group;");
        }
        buf++; if (buf == STAGES) buf = 0;
    }

    float* P = part + (size_t)split * B_ * QKV_N;
    store_partial(P, QKV_N, colbase + n0, m_off, n_off, gid, tig, acc);
}

// ---------------- Wo GEMM, split-K: grid (128, SK) ----------------
// partials layout: part[s][64][4096]
__global__ __launch_bounds__(256) void gemm_wo_sk(
    const float* __restrict__ A,      // g_attn
    const float* __restrict__ Wm,     // Wo
    float* __restrict__ part)
{
    __shared__ float As[STAGES][64][36];
    __shared__ float Bs[STAGES][32][36];
    const int tid = threadIdx.x;
    const int n0 = blockIdx.x * 32;
    const int split = blockIdx.y;
    const int K = D_;
    const int Ks = K / SK;            // 1024
    const int koff = split * Ks;
    const int T = Ks >> 5;
    const int lane = tid & 31, warp = tid >> 5;
    const int m_off = (warp & 3) * 16, n_off = (warp >> 2) * 16;
    const int gid = lane >> 2, tig = lane & 3;
    const float* A0 = A + koff;
    const float* W0 = Wm + (size_t)n0 * K + koff;

    float acc[2][4] = {};

    load_tile(As, Bs, 0, A0, K, W0, K, tid);
    load_tile(As, Bs, 1, A0 + 32, K, W0 + 32, K, tid);

    int buf = 0;
    for (int t = 0; t < T; t++) {
        asm volatile("cp.async.wait_group 1;");
        __syncthreads();
        compute_tile(As, Bs, buf, m_off, n_off, gid, tig, acc);
        int tn = t + 2;
        if (tn < T) {
            int nb = buf + 2; if (nb >= STAGES) nb -= STAGES;
            load_tile(As, Bs, nb, A0 + tn * 32, K, W0 + tn * 32, K, tid);
        } else {
            asm volatile("cp.async.commit_group;");
        }
        buf++; if (buf == STAGES) buf = 0;
    }

    float* P = part + (size_t)split * B_ * D_;
    store_partial(P, D_, n0, m_off, n_off, gid, tig, acc);
}

// ---------------- gate GEMM, split-K: grid (128, SK), K=8192 ----------------
// A = concat([x, oproj]) read directly. partials layout: part[s][64][4096]
__global__ __launch_bounds__(256) void gemm_gate_sk(
    const float* __restrict__ x,
    const float* __restrict__ oproj,
    const float* __restrict__ Wm,     // gate_w [4096, 8192]
    float* __restrict__ part)
{
    __shared__ float As[STAGES][64][36];
    __shared__ float Bs[STAGES][32][36];
    const int tid = threadIdx.x;
    const int n0 = blockIdx.x * 32;
    const int split = blockIdx.y;
    const int K = 2 * D_;
    const int Ks = K / SK;            // 2048
    const int koff = split * Ks;
    const int T = Ks >> 5;            // 64
    const int lane = tid & 31, warp = tid >> 5;
    const int m_off = (warp & 3) * 16, n_off = (warp >> 2) * 16;
    const int gid = lane >> 2, tig = lane & 3;
    const float* W0 = Wm + (size_t)n0 * K + koff;

    float acc[2][4] = {};

    // A-tile for global k0: x if k0 < 4096 else oproj (both row stride 4096)
    {
        int k0 = koff;
        const float* At0 = (k0 < D_) ? (x + k0) : (oproj + (k0 - D_));
        int k1 = koff + 32;
        const float* At1 = (k1 < D_) ? (x + k1) : (oproj + (k1 - D_));
        load_tile(As, Bs, 0, At0, D_, W0, K, tid);
        load_tile(As, Bs, 1, At1, D_, W0 + 32, K, tid);
    }

    int buf = 0;
    for (int t = 0; t < T; t++) {
        asm volatile("cp.async.wait_group 1;");
        __syncthreads();
        compute_tile(As, Bs, buf, m_off, n_off, gid, tig, acc);
        int tn = t + 2;
        if (tn < T) {
            int k0 = koff + tn * 32;
            const float* Atile = (k0 < D_) ? (x + k0) : (oproj + (k0 - D_));
            int nb = buf + 2; if (nb >= STAGES) nb -= STAGES;
            load_tile(As, Bs, nb, Atile, D_, W0 + tn * 32, K, tid);
        } else {
            asm volatile("cp.async.commit_group;");
        }
        buf++; if (buf == STAGES) buf = 0;
    }

    float* P = part + (size_t)split * B_ * D_;
    store_partial(P, D_, n0, m_off, n_off, gid, tig, acc);
}

// ---------------- QKV reduce + RoPE: sum SK partials, rotate q/k pairs -------------
// One thread per (row, pair): 64 * 3072 threads.
__global__ void reduce_rope_kernel(const float* __restrict__ part,
                                   float* __restrict__ q, float* __restrict__ kn,
                                   float* __restrict__ vn,
                                   const int* __restrict__ pos_p) {
    const int idx = blockIdx.x * 256 + threadIdx.x;
    const int PAIRS = QKV_N / 2;  // 3072
    if (idx >= B_ * PAIRS) return;
    const int row = idx / PAIRS;
    const int col = (idx - row * PAIRS) * 2;

    float s0 = 0.0f, s1 = 0.0f;
    #pragma unroll
    for (int s = 0; s < SK; s++) {
        const float* P = part + (size_t)s * B_ * QKV_N + (size_t)row * QKV_N + col;
        s0 += P[0];
        s1 += P[1];
    }

    if (col < D_ + 1024) {
        // q or knew: apply RoPE; pair index within head
        const int i = (col >> 1) & 63;
        const float pos = (float)(*pos_p);
        const float inv = 1.0f / powf(10000.0f, (float)(2 * i) / 128.0f);
        const float ang = pos * inv;
        float sn, cs;
        sincosf(ang, &sn, &cs);
        float r0 = s0 * cs - s1 * sn;
        float r1 = s0 * sn + s1 * cs;
        if (col < D_) {
            q[(size_t)row * D_ + col]     = r0;
            q[(size_t)row * D_ + col + 1] = r1;
        } else {
            int lc = col - D_;
            kn[(size_t)row * 1024 + lc]     = r0;
            kn[(size_t)row * 1024 + lc + 1] = r1;
        }
    } else {
        int lc = col - (D_ + 1024);
        vn[(size_t)row * 1024 + lc]     = s0;
        vn[(size_t)row * 1024 + lc + 1] = s1;
    }
}

// ---------------- Wo reduce: oproj = sum of SK partials (float4) -------------------
__global__ void reduce_wo_kernel(const float* __restrict__ part, float* __restrict__ oproj) {
    const int idx = blockIdx.x * 256 + threadIdx.x;   // float4 index
    if (idx >= B_ * D_ / 4) return;
    float4 a = ((const float4*)part)[idx];
    #pragma unroll
    for (int s = 1; s < SK; s++) {
        float4 b = ((const float4*)(part + (size_t)s * B_ * D_))[idx];
        a.x += b.x; a.y += b.y; a.z += b.z; a.w += b.w;
    }
    ((float4*)oproj)[idx] = a;
}

// ---------------- gate epilogue: out = x + sigmoid(sum + bias) * oproj -------------
__global__ void gate_epilogue_kernel(const float* __restrict__ part,
                                     const float* __restrict__ bias,
                                     const float* __restrict__ x,
                                     const float* __restrict__ oproj,
                                     float* __restrict__ out) {
    const int idx = blockIdx.x * 256 + threadIdx.x;   // float4 index
    if (idx >= B_ * D_ / 4) return;
    float4 z = ((const float4*)part)[idx];
    #pragma unroll
    for (int s = 1; s < SK; s++) {
        float4 b = ((const float4*)(part + (size_t)s * B_ * D_))[idx];
        z.x += b.x; z.y += b.y; z.z += b.z; z.w += b.w;
    }
    const int col = (idx * 4) & (D_ - 1);
    float4 bi = *(const float4*)(bias + col);
    float4 xv = ((const float4*)x)[idx];
    float4 op = ((const float4*)oproj)[idx];
    float4 o;
    o.x = xv.x + op.x / (1.0f + __expf(-(z.x + bi.x)));
    o.y = xv.y + op.y / (1.0f + __expf(-(z.y + bi.y)));
    o.z = xv.z + op.z / (1.0f + __expf(-(z.z + bi.z)));
    o.w = xv.w + op.w / (1.0f + __expf(-(z.w + bi.w)));
    ((float4*)out)[idx] = o;
}

// ---------------- attention: one block per (hkv, b); 256 threads (8 warps) ---------
// Effective keys: w=0..2046 -> cache slot w+1 (drop oldest); w=2047 -> k_new/v_new.
__global__ void attn_kernel(const float* __restrict__ q,
                            const float* __restrict__ knew,
                            const float* __restrict__ vnew,
                            const float* __restrict__ kc,
                            const float* __restrict__ vc,
                            float* __restrict__ out) {
    const int hkv = blockIdx.x, b = blockIdx.y;
    __shared__ float s[G_][W_];        // 32 KB scores/probs
    __shared__ float red[G_][64];
    __shared__ float o_acc[G_][DH_];
    __shared__ float sm[G_];
    const int tid = threadIdx.x;
    const int lane = tid & 31, warp = tid >> 5;

    for (int i = tid; i < G_ * DH_; i += 256) ((float*)o_acc)[i] = 0.0f;

    float qr[G_][4];
    const float* qbase = q + (size_t)b * D_ + (size_t)hkv * G_ * DH_;
    #pragma unroll
    for (int g = 0; g < G_; g++) {
        float4 t = *(const float4*)(qbase + g * DH_ + lane * 4);
        qr[g][0] = t.x; qr[g][1] = t.y; qr[g][2] = t.z; qr[g][3] = t.w;
    }
    const float scale = 0.08838834764831845f;  // 128^-0.5
    const size_t cbase = ((size_t)b * HKV_ + hkv) * W_ * DH_;
    const float* knew_r = knew + ((size_t)b * HKV_ + hkv) * DH_;
    const float* vnew_r = vnew + ((size_t)b * HKV_ + hkv) * DH_;

    __syncthreads();

    // ---- pass 1: scores (2 rows in flight per warp) ----
    for (int w = warp; w < W_; w += 16) {
        const int w2 = w + 8;
        const float* krow1 = (w  < W_ - 1) ? (kc + cbase + (size_t)(w  + 1) * DH_) : knew_r;
        const float* krow2 = (w2 < W_ - 1) ? (kc + cbase + (size_t)(w2 + 1) * DH_) : knew_r;
        float4 ka = *(const float4*)(krow1 + lane * 4);
        float4 kb = *(const float4*)(krow2 + lane * 4);
        float p0 = qr[0][0]*ka.x + qr[0][1]*ka.y + qr[0][2]*ka.z + qr[0][3]*ka.w;
        float p1 = qr[1][0]*ka.x + qr[1][1]*ka.y + qr[1][2]*ka.z + qr[1][3]*ka.w;
        float p2 = qr[2][0]*ka.x + qr[2][1]*ka.y + qr[2][2]*ka.z + qr[2][3]*ka.w;
        float p3 = qr[3][0]*ka.x + qr[3][1]*ka.y + qr[3][2]*ka.z + qr[3][3]*ka.w;
        float r0 = qr[0][0]*kb.x + qr[0][1]*kb.y + qr[0][2]*kb.z + qr[0][3]*kb.w;
        float r1 = qr[1][0]*kb.x + qr[1][1]*kb.y + qr[1][2]*kb.z + qr[1][3]*kb.w;
        float r2 = qr[2][0]*kb.x + qr[2][1]*kb.y + qr[2][2]*kb.z + qr[2][3]*kb.w;
        float r3 = qr[3][0]*kb.x + qr[3][1]*kb.y + qr[3][2]*kb.z + qr[3][3]*kb.w;
        #pragma unroll
        for (int off = 16; off; off >>= 1) {
            p0 += __shfl_xor_sync(0xffffffffu, p0, off);
            p1 += __shfl_xor_sync(0xffffffffu, p1, off);
            p2 += __shfl_xor_sync(0xffffffffu, p2, off);
            p3 += __shfl_xor_sync(0xffffffffu, p3, off);
            r0 += __shfl_xor_sync(0xffffffffu, r0, off);
            r1 += __shfl_xor_sync(0xffffffffu, r1, off);
            r2 += __shfl_xor_sync(0xffffffffu, r2, off);
            r3 += __shfl_xor_sync(0xffffffffu, r3, off);
        }
        if (lane == 0) {
            s[0][w]  = p0 * scale; s[1][w]  = p1 * scale;
            s[2][w]  = p2 * scale; s[3][w]  = p3 * scale;
            s[0][w2] = r0 * scale; s[1][w2] = r1 * scale;
            s[2][w2] = r2 * scale; s[3][w2] = r3 * scale;
        }
    }
    __syncthreads();

    // ---- softmax (64 threads per head) ----
    {
        const int g = tid >> 6, t = tid & 63;
        float lm = -1e30f;
        for (int i = t; i < W_; i += 64) lm = fmaxf(lm, s[g][i]);
        red[g][t] = lm;
        __syncthreads();
        for (int st = 32; st; st >>= 1) {
            if (t < st) red[g][t] = fmaxf(red[g][t], red[g][t + st]);
            __syncthreads();
        }
        const float m = red[g][0];
        float ls = 0.0f;
        for (int i = t; i < W_; i += 64) {
            float e = __expf(s[g][i] - m);
            s[g][i] = e;
            ls += e;
        }
        __syncthreads();
        red[g][t] = ls;
        __syncthreads();
        for (int st = 32; st; st >>= 1) {
            if (t < st) red[g][t] += red[g][t + st];
            __syncthreads();
        }
        if (t == 0) sm[g] = red[g][0];
        __syncthreads();
    }

    // ---- pass 2: p @ V (2 rows in flight per warp) ----
    float acc[G_][4] = {};
    for (int w = warp; w < W_; w += 16) {
        const int w2 = w + 8;
        const float* vrow1 = (w  < W_ - 1) ? (vc + cbase + (size_t)(w  + 1) * DH_) : vnew_r;
        const float* vrow2 = (w2 < W_ - 1) ? (vc + cbase + (size_t)(w2 + 1) * DH_) : vnew_r;
        float4 va = *(const float4*)(vrow1 + lane * 4);
        float4 vb = *(const float4*)(vrow2 + lane * 4);
        #pragma unroll
        for (int g = 0; g < G_; g++) {
            float pa = s[g][w], pb = s[g][w2];
            acc[g][0] += pa * va.x + pb * vb.x;
            acc[g][1] += pa * va.y + pb * vb.y;
            acc[g][2] += pa * va.z + pb * vb.z;
            acc[g][3] += pa * va.w + pb * vb.w;
        }
    }
    #pragma unroll
    for (int g = 0; g < G_; g++) {
        atomicAdd(&o_acc[g][lane * 4 + 0], acc[g][0]);
        atomicAdd(&o_acc[g][lane * 4 + 1], acc[g][1]);
        atomicAdd(&o_acc[g][lane * 4 + 2], acc[g][2]);
        atomicAdd(&o_acc[g][lane * 4 + 3], acc[g][3]);
    }
    __syncthreads();

    float* obase = out + (size_t)b * D_ + (size_t)hkv * G_ * DH_;
    for (int i = tid; i < G_ * DH_; i += 256) {
        int g = i >> 7, d = i & 127;
        obase[g * DH_ + d] = o_acc[g][d] / sm[g];
    }
}

// ---------------- launch ----------------
extern "C" void kernel_launch(void* const* d_in, const int* in_sizes, int n_in,
                              void* d_out, int out_size) {
    const float* x   = (const float*)d_in[0];
    const float* kc  = (const float*)d_in[1];
    const float* vc  = (const float*)d_in[2];
    const float* Wq  = (const float*)d_in[3];
    const float* Wk  = (const float*)d_in[4];
    const float* Wv  = (const float*)d_in[5];
    const float* Wo  = (const float*)d_in[6];
    const float* gw  = (const float*)d_in[7];
    const float* gb  = (const float*)d_in[8];
    const int*   pos = (const int*)d_in[9];
    float* out = (float*)d_out;

    float *qb, *knb, *vnb, *attnb, *opb, *partb;
    cudaGetSymbolAddress((void**)&qb,    g_q);
    cudaGetSymbolAddress((void**)&knb,   g_knew);
    cudaGetSymbolAddress((void**)&vnb,   g_vnew);
    cudaGetSymbolAddress((void**)&attnb, g_attn);
    cudaGetSymbolAddress((void**)&opb,   g_oproj);
    cudaGetSymbolAddress((void**)&partb, g_part);

    // QKV projections, split-K x4 -> partials
    gemm_qkv_sk<<<dim3(192, SK), 256>>>(x, Wq, Wk, Wv, partb);

    // Reduce partials + RoPE
    {
        int total = B_ * (QKV_N / 2);   // 196608 pair-threads
        reduce_rope_kernel<<<(total + 255) / 256, 256>>>(partb, qb, knb, vnb, pos);
    }

    // Attention
    attn_kernel<<<dim3(HKV_, B_), 256>>>(qb, knb, vnb, kc, vc, attnb);

    // o_proj = attn @ Wo^T  (split-K x4 -> partials -> reduce)
    gemm_wo_sk<<<dim3(128, SK), 256>>>(attnb, Wo, partb);
    reduce_wo_kernel<<<(B_ * D_ / 4 + 255) / 256, 256>>>(partb, opb);

    // Gate GEMM, split-K x4 -> partials -> fused sigmoid/residual epilogue
    gemm_gate_sk<<<dim3(128, SK), 256>>>(x, opb, gw, partb);
    gate_epilogue_kernel<<<(B_ * D_ / 4 + 255) / 256, 256>>>(partb, gb, x, opb, out);
}

// round 10
// speedup vs baseline: 3.5029x; 1.1673x over previous
#include <cuda_runtime.h>
#include <math.h>

#define B_   64
#define D_   4096
#define HKV_ 8
#define G_   4
#define DH_  128
#define W_   2048
#define STAGES 3
#define SK   8                     // split-K factor
#define QKV_N (D_ + 2 * HKV_ * DH_)   // 6144 concat output cols (q | knew | vnew)

// ---------------- scratch (device globals; no allocations allowed) ----------------
__device__ float g_q    [B_ * D_];             // q (RoPE'd)
__device__ float g_knew [B_ * HKV_ * DH_];     // new k (RoPE'd)
__device__ float g_vnew [B_ * HKV_ * DH_];     // new v
__device__ float g_attn [B_ * D_];             // attention output
__device__ float g_oproj[B_ * D_];             // attn @ Wo^T
__device__ float g_part [SK * B_ * QKV_N];     // split-K partials (reused by all GEMMs)

// ================= tf32 tensor-core GEMM machinery ============
// 256 threads (8 warps), block tile 64(M) x 32(N), k-tile 32, 3-stage cp.async.
// warp grid: 4 (M) x 2 (N); warp tile 16x16 = 2x mma.m16n8k8.

__device__ __forceinline__ unsigned f2tf32(float x) {
    unsigned y;
    asm("cvt.rna.tf32.f32 %0, %1;" : "=r"(y) : "f"(x));
    return y;
}

__device__ __forceinline__ void mma_tf32(float& c0, float& c1, float& c2, float& c3,
                                         unsigned a0, unsigned a1, unsigned a2, unsigned a3,
                                         unsigned b0, unsigned b1) {
    asm volatile("mma.sync.aligned.m16n8k8.row.col.f32.tf32.tf32.f32 "
                 "{%0,%1,%2,%3}, {%4,%5,%6,%7}, {%8,%9}, {%0,%1,%2,%3};"
                 : "+f"(c0), "+f"(c1), "+f"(c2), "+f"(c3)
                 : "r"(a0), "r"(a1), "r"(a2), "r"(a3), "r"(b0), "r"(b1));
}

#define CP16(dst_smem_u32, src_ptr) \
    asm volatile("cp.async.cg.shared.global [%0], [%1], 16;" :: "r"(dst_smem_u32), "l"(src_ptr))

__device__ __forceinline__ void load_tile(float As[STAGES][64][36], float Bs[STAGES][32][36],
                                          int buf,
                                          const float* __restrict__ Atile, int lda,
                                          const float* __restrict__ Wtile, int ldw, int tid)
{
    #pragma unroll
    for (int j = 0; j < 2; j++) {
        int f = tid + j * 256;
        int row = f >> 3, c4 = f & 7;
        unsigned dst = (unsigned)__cvta_generic_to_shared(&As[buf][row][c4 * 4]);
        CP16(dst, Atile + (size_t)row * lda + c4 * 4);
    }
    {
        int row = tid >> 3, c4 = tid & 7;
        unsigned dst = (unsigned)__cvta_generic_to_shared(&Bs[buf][row][c4 * 4]);
        CP16(dst, Wtile + (size_t)row * ldw + c4 * 4);
    }
    asm volatile("cp.async.commit_group;");
}

__device__ __forceinline__ void compute_tile(float As[STAGES][64][36], float Bs[STAGES][32][36],
                                             int buf, int m_off, int n_off, int gid, int tig,
                                             float acc[2][4])
{
    #pragma unroll
    for (int kk = 0; kk < 32; kk += 8) {
        unsigned a0 = f2tf32(As[buf][m_off + gid    ][kk + tig    ]);
        unsigned a1 = f2tf32(As[buf][m_off + gid + 8][kk + tig    ]);
        unsigned a2 = f2tf32(As[buf][m_off + gid    ][kk + tig + 4]);
        unsigned a3 = f2tf32(As[buf][m_off + gid + 8][kk + tig + 4]);
        #pragma unroll
        for (int t = 0; t < 2; t++) {
            int n = n_off + t * 8;
            unsigned b0 = f2tf32(Bs[buf][n + gid][kk + tig    ]);
            unsigned b1 = f2tf32(Bs[buf][n + gid][kk + tig + 4]);
            mma_tf32(acc[t][0], acc[t][1], acc[t][2], acc[t][3],
                     a0, a1, a2, a3, b0, b1);
        }
    }
}

// Store 64x32 partial accumulator block into partial buffer (row stride ldc).
__device__ __forceinline__ void store_partial(float* __restrict__ P, int ldc, int col0,
                                              int m_off, int n_off, int gid, int tig,
                                              float acc[2][4])
{
    #pragma unroll
    for (int t = 0; t < 2; t++) {
        int row = m_off + gid;
        int col = col0 + n_off + t * 8 + 2 * tig;
        P[(size_t)row * ldc + col]           = acc[t][0];
        P[(size_t)row * ldc + col + 1]       = acc[t][1];
        P[(size_t)(row + 8) * ldc + col]     = acc[t][2];
        P[(size_t)(row + 8) * ldc + col + 1] = acc[t][3];
    }
}

// ---------------- fused QKV projection, split-K: grid (192, SK) ----------------
// bx [0,128): q cols; [128,160): knew; [160,192): vnew. Partials layout:
// part[s][64][6144] with col concat (q | knew | vnew).
__global__ __launch_bounds__(256) void gemm_qkv_sk(
    const float* __restrict__ x,
    const float* __restrict__ Wq, const float* __restrict__ Wk, const float* __restrict__ Wv,
    float* __restrict__ part)
{
    __shared__ float As[STAGES][64][36];
    __shared__ float Bs[STAGES][32][36];
    const int tid = threadIdx.x;
    const int bx = blockIdx.x;
    const int split = blockIdx.y;
    const float* Wm; int n0, colbase;
    if (bx < 128)      { Wm = Wq; colbase = 0;    n0 = bx * 32; }
    else if (bx < 160) { Wm = Wk; colbase = D_;   n0 = (bx - 128) * 32; }
    else               { Wm = Wv; colbase = D_ + 1024; n0 = (bx - 160) * 32; }
    const int K = D_;
    const int Ks = K / SK;              // 512
    const int koff = split * Ks;
    const int T = Ks >> 5;              // 16
    const int lane = tid & 31, warp = tid >> 5;
    const int m_off = (warp & 3) * 16, n_off = (warp >> 2) * 16;
    const int gid = lane >> 2, tig = lane & 3;
    const float* A0 = x + koff;
    const float* W0 = Wm + (size_t)n0 * K + koff;

    float acc[2][4] = {};

    load_tile(As, Bs, 0, A0, K, W0, K, tid);
    load_tile(As, Bs, 1, A0 + 32, K, W0 + 32, K, tid);

    int buf = 0;
    for (int t = 0; t < T; t++) {
        asm volatile("cp.async.wait_group 1;");
        __syncthreads();
        compute_tile(As, Bs, buf, m_off, n_off, gid, tig, acc);
        int tn = t + 2;
        if (tn < T) {
            int nb = buf + 2; if (nb >= STAGES) nb -= STAGES;
            load_tile(As, Bs, nb, A0 + tn * 32, K, W0 + tn * 32, K, tid);
        } else {
            asm volatile("cp.async.commit_group;");
        }
        buf++; if (buf == STAGES) buf = 0;
    }

    float* P = part + (size_t)split * B_ * QKV_N;
    store_partial(P, QKV_N, colbase + n0, m_off, n_off, gid, tig, acc);
}

// ---------------- Wo GEMM, split-K: grid (128, SK) ----------------
// partials layout: part[s][64][4096]
__global__ __launch_bounds__(256) void gemm_wo_sk(
    const float* __restrict__ A,      // g_attn
    const float* __restrict__ Wm,     // Wo
    float* __restrict__ part)
{
    __shared__ float As[STAGES][64][36];
    __shared__ float Bs[STAGES][32][36];
    const int tid = threadIdx.x;
    const int n0 = blockIdx.x * 32;
    const int split = blockIdx.y;
    const int K = D_;
    const int Ks = K / SK;            // 512
    const int koff = split * Ks;
    const int T = Ks >> 5;            // 16
    const int lane = tid & 31, warp = tid >> 5;
    const int m_off = (warp & 3) * 16, n_off = (warp >> 2) * 16;
    const int gid = lane >> 2, tig = lane & 3;
    const float* A0 = A + koff;
    const float* W0 = Wm + (size_t)n0 * K + koff;

    float acc[2][4] = {};

    load_tile(As, Bs, 0, A0, K, W0, K, tid);
    load_tile(As, Bs, 1, A0 + 32, K, W0 + 32, K, tid);

    int buf = 0;
    for (int t = 0; t < T; t++) {
        asm volatile("cp.async.wait_group 1;");
        __syncthreads();
        compute_tile(As, Bs, buf, m_off, n_off, gid, tig, acc);
        int tn = t + 2;
        if (tn < T) {
            int nb = buf + 2; if (nb >= STAGES) nb -= STAGES;
            load_tile(As, Bs, nb, A0 + tn * 32, K, W0 + tn * 32, K, tid);
        } else {
            asm volatile("cp.async.commit_group;");
        }
        buf++; if (buf == STAGES) buf = 0;
    }

    float* P = part + (size_t)split * B_ * D_;
    store_partial(P, D_, n0, m_off, n_off, gid, tig, acc);
}

// ---------------- gate GEMM, split-K: grid (128, SK), K=8192 ----------------
// A = concat([x, oproj]) read directly. partials layout: part[s][64][4096]
__global__ __launch_bounds__(256) void gemm_gate_sk(
    const float* __restrict__ x,
    const float* __restrict__ oproj,
    const float* __restrict__ Wm,     // gate_w [4096, 8192]
    float* __restrict__ part)
{
    __shared__ float As[STAGES][64][36];
    __shared__ float Bs[STAGES][32][36];
    const int tid = threadIdx.x;
    const int n0 = blockIdx.x * 32;
    const int split = blockIdx.y;
    const int K = 2 * D_;
    const int Ks = K / SK;            // 1024
    const int koff = split * Ks;
    const int T = Ks >> 5;            // 32
    const int lane = tid & 31, warp = tid >> 5;
    const int m_off = (warp & 3) * 16, n_off = (warp >> 2) * 16;
    const int gid = lane >> 2, tig = lane & 3;
    const float* W0 = Wm + (size_t)n0 * K + koff;

    float acc[2][4] = {};

    // A-tile for global k0: x if k0 < 4096 else oproj (both row stride 4096)
    {
        int k0 = koff;
        const float* At0 = (k0 < D_) ? (x + k0) : (oproj + (k0 - D_));
        int k1 = koff + 32;
        const float* At1 = (k1 < D_) ? (x + k1) : (oproj + (k1 - D_));
        load_tile(As, Bs, 0, At0, D_, W0, K, tid);
        load_tile(As, Bs, 1, At1, D_, W0 + 32, K, tid);
    }

    int buf = 0;
    for (int t = 0; t < T; t++) {
        asm volatile("cp.async.wait_group 1;");
        __syncthreads();
        compute_tile(As, Bs, buf, m_off, n_off, gid, tig, acc);
        int tn = t + 2;
        if (tn < T) {
            int k0 = koff + tn * 32;
            const float* Atile = (k0 < D_) ? (x + k0) : (oproj + (k0 - D_));
            int nb = buf + 2; if (nb >= STAGES) nb -= STAGES;
            load_tile(As, Bs, nb, Atile, D_, W0 + tn * 32, K, tid);
        } else {
            asm volatile("cp.async.commit_group;");
        }
        buf++; if (buf == STAGES) buf = 0;
    }

    float* P = part + (size_t)split * B_ * D_;
    store_partial(P, D_, n0, m_off, n_off, gid, tig, acc);
}

// ---------------- QKV reduce + RoPE: sum SK partials, rotate q/k pairs -------------
// One thread per (row, pair): 64 * 3072 threads.
__global__ void reduce_rope_kernel(const float* __restrict__ part,
                                   float* __restrict__ q, float* __restrict__ kn,
                                   float* __restrict__ vn,
                                   const int* __restrict__ pos_p) {
    const int idx = blockIdx.x * 256 + threadIdx.x;
    const int PAIRS = QKV_N / 2;  // 3072
    if (idx >= B_ * PAIRS) return;
    const int row = idx / PAIRS;
    const int col = (idx - row * PAIRS) * 2;

    float s0 = 0.0f, s1 = 0.0f;
    #pragma unroll
    for (int s = 0; s < SK; s++) {
        const float* P = part + (size_t)s * B_ * QKV_N + (size_t)row * QKV_N + col;
        s0 += P[0];
        s1 += P[1];
    }

    if (col < D_ + 1024) {
        // q or knew: apply RoPE; pair index within head
        const int i = (col >> 1) & 63;
        const float pos = (float)(*pos_p);
        const float inv = 1.0f / powf(10000.0f, (float)(2 * i) / 128.0f);
        const float ang = pos * inv;
        float sn, cs;
        sincosf(ang, &sn, &cs);
        float r0 = s0 * cs - s1 * sn;
        float r1 = s0 * sn + s1 * cs;
        if (col < D_) {
            q[(size_t)row * D_ + col]     = r0;
            q[(size_t)row * D_ + col + 1] = r1;
        } else {
            int lc = col - D_;
            kn[(size_t)row * 1024 + lc]     = r0;
            kn[(size_t)row * 1024 + lc + 1] = r1;
        }
    } else {
        int lc = col - (D_ + 1024);
        vn[(size_t)row * 1024 + lc]     = s0;
        vn[(size_t)row * 1024 + lc + 1] = s1;
    }
}

// ---------------- Wo reduce: oproj = sum of SK partials (float4) -------------------
__global__ void reduce_wo_kernel(const float* __restrict__ part, float* __restrict__ oproj) {
    const int idx = blockIdx.x * 256 + threadIdx.x;   // float4 index
    if (idx >= B_ * D_ / 4) return;
    float4 a = ((const float4*)part)[idx];
    #pragma unroll
    for (int s = 1; s < SK; s++) {
        float4 b = ((const float4*)(part + (size_t)s * B_ * D_))[idx];
        a.x += b.x; a.y += b.y; a.z += b.z; a.w += b.w;
    }
    ((float4*)oproj)[idx] = a;
}

// ---------------- gate epilogue: out = x + sigmoid(sum + bias) * oproj -------------
__global__ void gate_epilogue_kernel(const float* __restrict__ part,
                                     const float* __restrict__ bias,
                                     const float* __restrict__ x,
                                     const float* __restrict__ oproj,
                                     float* __restrict__ out) {
    const int idx = blockIdx.x * 256 + threadIdx.x;   // float4 index
    if (idx >= B_ * D_ / 4) return;
    float4 z = ((const float4*)part)[idx];
    #pragma unroll
    for (int s = 1; s < SK; s++) {
        float4 b = ((const float4*)(part + (size_t)s * B_ * D_))[idx];
        z.x += b.x; z.y += b.y; z.z += b.z; z.w += b.w;
    }
    const int col = (idx * 4) & (D_ - 1);
    float4 bi = *(const float4*)(bias + col);
    float4 xv = ((const float4*)x)[idx];
    float4 op = ((const float4*)oproj)[idx];
    float4 o;
    o.x = xv.x + op.x / (1.0f + __expf(-(z.x + bi.x)));
    o.y = xv.y + op.y / (1.0f + __expf(-(z.y + bi.y)));
    o.z = xv.z + op.z / (1.0f + __expf(-(z.z + bi.z)));
    o.w = xv.w + op.w / (1.0f + __expf(-(z.w + bi.w)));
    ((float4*)out)[idx] = o;
}

// ---------------- attention: one block per (hkv, b); 256 threads (8 warps) ---------
// Effective keys: w=0..2046 -> cache slot w+1 (drop oldest); w=2047 -> k_new/v_new.
// 4 key/value rows in flight per warp for memory-latency hiding.
__global__ void attn_kernel(const float* __restrict__ q,
                            const float* __restrict__ knew,
                            const float* __restrict__ vnew,
                            const float* __restrict__ kc,
                            const float* __restrict__ vc,
                            float* __restrict__ out) {
    const int hkv = blockIdx.x, b = blockIdx.y;
    __shared__ float s[G_][W_];        // 32 KB scores/probs
    __shared__ float red[G_][64];
    __shared__ float o_acc[G_][DH_];
    __shared__ float sm[G_];
    const int tid = threadIdx.x;
    const int lane = tid & 31, warp = tid >> 5;

    for (int i = tid; i < G_ * DH_; i += 256) ((float*)o_acc)[i] = 0.0f;

    float qr[G_][4];
    const float* qbase = q + (size_t)b * D_ + (size_t)hkv * G_ * DH_;
    #pragma unroll
    for (int g = 0; g < G_; g++) {
        float4 t = *(const float4*)(qbase + g * DH_ + lane * 4);
        qr[g][0] = t.x; qr[g][1] = t.y; qr[g][2] = t.z; qr[g][3] = t.w;
    }
    const float scale = 0.08838834764831845f;  // 128^-0.5
    const size_t cbase = ((size_t)b * HKV_ + hkv) * W_ * DH_;
    const float* knew_r = knew + ((size_t)b * HKV_ + hkv) * DH_;
    const float* vnew_r = vnew + ((size_t)b * HKV_ + hkv) * DH_;

    __syncthreads();

    // ---- pass 1: scores (4 rows in flight per warp) ----
    for (int w = warp; w < W_; w += 32) {
        float4 kv[4];
        #pragma unroll
        for (int r = 0; r < 4; r++) {
            int wr = w + r * 8;
            const float* krow = (wr < W_ - 1) ? (kc + cbase + (size_t)(wr + 1) * DH_) : knew_r;
            kv[r] = *(const float4*)(krow + lane * 4);
        }
        float p[4][G_];
        #pragma unroll
        for (int r = 0; r < 4; r++) {
            #pragma unroll
            for (int g = 0; g < G_; g++)
                p[r][g] = qr[g][0]*kv[r].x + qr[g][1]*kv[r].y + qr[g][2]*kv[r].z + qr[g][3]*kv[r].w;
        }
        #pragma unroll
        for (int off = 16; off; off >>= 1) {
            #pragma unroll
            for (int r = 0; r < 4; r++) {
                #pragma unroll
                for (int g = 0; g < G_; g++)
                    p[r][g] += __shfl_xor_sync(0xffffffffu, p[r][g], off);
            }
        }
        if (lane == 0) {
            #pragma unroll
            for (int r = 0; r < 4; r++) {
                int wr = w + r * 8;
                #pragma unroll
                for (int g = 0; g < G_; g++)
                    s[g][wr] = p[r][g] * scale;
            }
        }
    }
    __syncthreads();

    // ---- softmax (64 threads per head) ----
    {
        const int g = tid >> 6, t = tid & 63;
        float lm = -1e30f;
        for (int i = t; i < W_; i += 64) lm = fmaxf(lm, s[g][i]);
        red[g][t] = lm;
        __syncthreads();
        for (int st = 32; st; st >>= 1) {
            if (t < st) red[g][t] = fmaxf(red[g][t], red[g][t + st]);
            __syncthreads();
        }
        const float m = red[g][0];
        float ls = 0.0f;
        for (int i = t; i < W_; i += 64) {
            float e = __expf(s[g][i] - m);
            s[g][i] = e;
            ls += e;
        }
        __syncthreads();
        red[g][t] = ls;
        __syncthreads();
        for (int st = 32; st; st >>= 1) {
            if (t < st) red[g][t] += red[g][t + st];
            __syncthreads();
        }
        if (t == 0) sm[g] = red[g][0];
        __syncthreads();
    }

    // ---- pass 2: p @ V (4 rows in flight per warp) ----
    float acc[G_][4] = {};
    for (int w = warp; w < W_; w += 32) {
        float4 vv[4];
        #pragma unroll
        for (int r = 0; r < 4; r++) {
            int wr = w + r * 8;
            const float* vrow = (wr < W_ - 1) ? (vc + cbase + (size_t)(wr + 1) * DH_) : vnew_r;
            vv[r] = *(const float4*)(vrow + lane * 4);
        }
        #pragma unroll
        for (int r = 0; r < 4; r++) {
            int wr = w + r * 8;
            #pragma unroll
            for (int g = 0; g < G_; g++) {
                float pw = s[g][wr];
                acc[g][0] += pw * vv[r].x;
                acc[g][1] += pw * vv[r].y;
                acc[g][2] += pw * vv[r].z;
                acc[g][3] += pw * vv[r].w;
            }
        }
    }
    #pragma unroll
    for (int g = 0; g < G_; g++) {
        atomicAdd(&o_acc[g][lane * 4 + 0], acc[g][0]);
        atomicAdd(&o_acc[g][lane * 4 + 1], acc[g][1]);
        atomicAdd(&o_acc[g][lane * 4 + 2], acc[g][2]);
        atomicAdd(&o_acc[g][lane * 4 + 3], acc[g][3]);
    }
    __syncthreads();

    float* obase = out + (size_t)b * D_ + (size_t)hkv * G_ * DH_;
    for (int i = tid; i < G_ * DH_; i += 256) {
        int g = i >> 7, d = i & 127;
        obase[g * DH_ + d] = o_acc[g][d] / sm[g];
    }
}

// ---------------- launch ----------------
extern "C" void kernel_launch(void* const* d_in, const int* in_sizes, int n_in,
                              void* d_out, int out_size) {
    const float* x   = (const float*)d_in[0];
    const float* kc  = (const float*)d_in[1];
    const float* vc  = (const float*)d_in[2];
    const float* Wq  = (const float*)d_in[3];
    const float* Wk  = (const float*)d_in[4];
    const float* Wv  = (const float*)d_in[5];
    const float* Wo  = (const float*)d_in[6];
    const float* gw  = (const float*)d_in[7];
    const float* gb  = (const float*)d_in[8];
    const int*   pos = (const int*)d_in[9];
    float* out = (float*)d_out;

    float *qb, *knb, *vnb, *attnb, *opb, *partb;
    cudaGetSymbolAddress((void**)&qb,    g_q);
    cudaGetSymbolAddress((void**)&knb,   g_knew);
    cudaGetSymbolAddress((void**)&vnb,   g_vnew);
    cudaGetSymbolAddress((void**)&attnb, g_attn);
    cudaGetSymbolAddress((void**)&opb,   g_oproj);
    cudaGetSymbolAddress((void**)&partb, g_part);

    // QKV projections, split-K x8 -> partials
    gemm_qkv_sk<<<dim3(192, SK), 256>>>(x, Wq, Wk, Wv, partb);

    // Reduce partials + RoPE
    {
        int total = B_ * (QKV_N / 2);   // 196608 pair-threads
        reduce_rope_kernel<<<(total + 255) / 256, 256>>>(partb, qb, knb, vnb, pos);
    }

    // Attention
    attn_kernel<<<dim3(HKV_, B_), 256>>>(qb, knb, vnb, kc, vc, attnb);

    // o_proj = attn @ Wo^T  (split-K x8 -> partials -> reduce)
    gemm_wo_sk<<<dim3(128, SK), 256>>>(attnb, Wo, partb);
    reduce_wo_kernel<<<(B_ * D_ / 4 + 255) / 256, 256>>>(partb, opb);

    // Gate GEMM, split-K x8 -> partials -> fused sigmoid/residual epilogue
    gemm_gate_sk<<<dim3(128, SK), 256>>>(x, opb, gw, partb);
    gate_epilogue_kernel<<<(B_ * D_ / 4 + 255) / 256, 256>>>(partb, gb, x, opb, out);
}